// round 2
// baseline (speedup 1.0000x reference)
#include <cuda_runtime.h>
#include <cstddef>

#define NSEQ   4096
#define BATCH  4
#define DIMSZ  1024
#define NHEAD  16
#define KLR    64
#define DH     64
#define MROWS  (NSEQ*BATCH)     /* 16384 */
#define QKVDIM (3*DIMSZ)        /* 3072  */

// ---------------- scratch (static device globals; no allocation) -------------
__device__ float g_qkv[(size_t)MROWS * QKVDIM];      // 201 MB
__device__ float g_kp [BATCH*NHEAD*KLR*DH];          // [bh][k][d]
__device__ float g_vp [BATCH*NHEAD*KLR*DH];
__device__ float g_ao [(size_t)MROWS * DIMSZ];       // 67 MB, (n,b,dim) layout

// ---------------- SGEMM: C = A(MxK) * B(KxN) + bias, all row-major -----------
// 128x128 block tile, BK=8, 256 threads, 8x8 per thread split as 2x2 of 4x4
// (float4 shared loads, conflict-free).
__global__ __launch_bounds__(256) void sgemm_bias(
    const float* __restrict__ A, const float* __restrict__ B,
    const float* __restrict__ bias, float* __restrict__ C,
    int M, int Ncols, int Kdim)
{
    constexpr int BM = 128, BN = 128, BK = 8;
    __shared__ float As[BK][BM];
    __shared__ float Bs[BK][BN];

    const int tid  = threadIdx.x;
    const int bm0  = blockIdx.y * BM;
    const int bn0  = blockIdx.x * BN;

    const int aRow = tid >> 1;            // 0..127
    const int aCol = (tid & 1) * 4;       // 0 or 4
    const int bRow = tid >> 5;            // 0..7
    const int bCol = (tid & 31) * 4;      // 0..124

    const int ty = tid >> 4;              // 0..15
    const int tx = tid & 15;              // 0..15

    float acc[8][8];
    #pragma unroll
    for (int i = 0; i < 8; i++)
        #pragma unroll
        for (int j = 0; j < 8; j++) acc[i][j] = 0.f;

    const float* Aptr = A + (size_t)bm0 * Kdim;

    for (int k0 = 0; k0 < Kdim; k0 += BK) {
        float4 a4 = *(const float4*)(Aptr + (size_t)aRow * Kdim + k0 + aCol);
        As[aCol + 0][aRow] = a4.x;
        As[aCol + 1][aRow] = a4.y;
        As[aCol + 2][aRow] = a4.z;
        As[aCol + 3][aRow] = a4.w;
        *(float4*)&Bs[bRow][bCol] =
            *(const float4*)(B + (size_t)(k0 + bRow) * Ncols + bn0 + bCol);
        __syncthreads();

        #pragma unroll
        for (int kk = 0; kk < BK; kk++) {
            float4 ra0 = *(const float4*)&As[kk][ty * 4];
            float4 ra1 = *(const float4*)&As[kk][64 + ty * 4];
            float4 rb0 = *(const float4*)&Bs[kk][tx * 4];
            float4 rb1 = *(const float4*)&Bs[kk][64 + tx * 4];
            float ra[8] = {ra0.x, ra0.y, ra0.z, ra0.w, ra1.x, ra1.y, ra1.z, ra1.w};
            float rb[8] = {rb0.x, rb0.y, rb0.z, rb0.w, rb1.x, rb1.y, rb1.z, rb1.w};
            #pragma unroll
            for (int i = 0; i < 8; i++)
                #pragma unroll
                for (int j = 0; j < 8; j++)
                    acc[i][j] += ra[i] * rb[j];
        }
        __syncthreads();
    }

    // epilogue: rows {bm0 + ih*64 + ty*4 + i}, cols {bn0 + jh*64 + tx*4 + j}
    #pragma unroll
    for (int ih = 0; ih < 2; ih++) {
        #pragma unroll
        for (int i = 0; i < 4; i++) {
            int row = bm0 + ih * 64 + ty * 4 + i;
            #pragma unroll
            for (int jh = 0; jh < 2; jh++) {
                int col = bn0 + jh * 64 + tx * 4;
                float4 o;
                o.x = acc[ih * 4 + i][jh * 4 + 0] + bias[col + 0];
                o.y = acc[ih * 4 + i][jh * 4 + 1] + bias[col + 1];
                o.z = acc[ih * 4 + i][jh * 4 + 2] + bias[col + 2];
                o.w = acc[ih * 4 + i][jh * 4 + 3] + bias[col + 3];
                *(float4*)(C + (size_t)row * Ncols + col) = o;
            }
        }
    }
}

// ---------------- low-rank projection: Kp/Vp[bh][k][d] = sum_n P[n][k]*S[n][d]
// grid.x = 64 (bh = b*16+h), grid.y = 2 (0 -> K via E, 1 -> V via F)
__global__ __launch_bounds__(256) void lowrank_proj(
    const float* __restrict__ E, const float* __restrict__ F)
{
    const int bh    = blockIdx.x;
    const int which = blockIdx.y;
    const int b     = bh >> 4;
    const int h     = bh & 15;

    const float* P   = which ? F : E;
    const int    off = (which ? 2 * DIMSZ : DIMSZ) + h * DH;
    float*       out = (which ? g_vp : g_kp) + bh * KLR * DH;

    __shared__ float Ps[64][64];
    __shared__ float Ss[64][64];

    const int tid = threadIdx.x;
    const int ty  = tid >> 4;   // k0 = ty*4
    const int tx  = tid & 15;   // d0 = tx*4

    float acc[4][4];
    #pragma unroll
    for (int i = 0; i < 4; i++)
        #pragma unroll
        for (int j = 0; j < 4; j++) acc[i][j] = 0.f;

    for (int n0 = 0; n0 < NSEQ; n0 += 64) {
        #pragma unroll 4
        for (int idx = tid; idx < 4096; idx += 256) {
            int nn = idx >> 6, c = idx & 63;
            Ps[nn][c] = P[(size_t)(n0 + nn) * KLR + c];
            Ss[nn][c] = g_qkv[((size_t)(n0 + nn) * BATCH + b) * QKVDIM + off + c];
        }
        __syncthreads();
        #pragma unroll 8
        for (int nn = 0; nn < 64; nn++) {
            float4 p4 = *(const float4*)&Ps[nn][ty * 4];
            float4 s4 = *(const float4*)&Ss[nn][tx * 4];
            float p[4] = {p4.x, p4.y, p4.z, p4.w};
            float s[4] = {s4.x, s4.y, s4.z, s4.w};
            #pragma unroll
            for (int i = 0; i < 4; i++)
                #pragma unroll
                for (int j = 0; j < 4; j++)
                    acc[i][j] += p[i] * s[j];
        }
        __syncthreads();
    }

    #pragma unroll
    for (int i = 0; i < 4; i++) {
        int k = ty * 4 + i;
        float4 o = {acc[i][0], acc[i][1], acc[i][2], acc[i][3]};
        *(float4*)&out[k * DH + tx * 4] = o;
    }
}

// ---------------- fused attention: dots -> softmax -> @V ---------------------
// grid: (NSEQ/16, 64 bh); 512 threads = 16 warps, one row per warp.
__global__ __launch_bounds__(512) void attn_kernel()
{
    const int bh = blockIdx.y;
    const int b  = bh >> 4;
    const int h  = bh & 15;
    const int n0 = blockIdx.x * 16;

    __shared__ float KpT[DH][KLR + 1];  // [d][k], padded
    __shared__ float Vs [KLR][DH];      // [k][d]
    __shared__ float qs [16][DH];
    __shared__ float as [16][KLR];

    const int tid = threadIdx.x;
    const float* Kp = g_kp + bh * KLR * DH;
    const float* Vp = g_vp + bh * KLR * DH;

    for (int idx = tid; idx < KLR * DH; idx += 512) {
        int k = idx >> 6, d = idx & 63;
        KpT[d][k] = Kp[idx];
        Vs[k][d]  = Vp[idx];
    }
    for (int idx = tid; idx < 16 * DH; idx += 512) {
        int r = idx >> 6, d = idx & 63;
        qs[r][d] = g_qkv[((size_t)(n0 + r) * BATCH + b) * QKVDIM + h * DH + d];
    }
    __syncthreads();

    const int w = tid >> 5;      // row within block
    const int l = tid & 31;

    float a0 = 0.f, a1 = 0.f;
    #pragma unroll
    for (int d = 0; d < DH; d++) {
        float qv = qs[w][d];
        a0 += qv * KpT[d][l];
        a1 += qv * KpT[d][l + 32];
    }
    const float scale = 0.125f;   // DH^-0.5
    a0 *= scale; a1 *= scale;

    float m = fmaxf(a0, a1);
    #pragma unroll
    for (int o = 16; o > 0; o >>= 1) m = fmaxf(m, __shfl_xor_sync(0xffffffffu, m, o));
    float e0 = __expf(a0 - m), e1 = __expf(a1 - m);
    float s = e0 + e1;
    #pragma unroll
    for (int o = 16; o > 0; o >>= 1) s += __shfl_xor_sync(0xffffffffu, s, o);
    float inv = 1.0f / s;
    as[w][l]      = e0 * inv;
    as[w][l + 32] = e1 * inv;
    __syncwarp();

    float o0 = 0.f, o1 = 0.f;
    #pragma unroll
    for (int k = 0; k < KLR; k++) {
        float av = as[w][k];
        o0 += av * Vs[k][l];
        o1 += av * Vs[k][l + 32];
    }
    size_t base = ((size_t)(n0 + w) * BATCH + b) * DIMSZ + h * DH;
    g_ao[base + l]      = o0;
    g_ao[base + l + 32] = o1;
}

// ---------------- launch -----------------------------------------------------
extern "C" void kernel_launch(void* const* d_in, const int* in_sizes, int n_in,
                              void* d_out, int out_size)
{
    const float* x    = (const float*)d_in[0];
    const float* E    = (const float*)d_in[1];
    const float* F    = (const float*)d_in[2];
    const float* Wqkv = (const float*)d_in[3];
    const float* bqkv = (const float*)d_in[4];
    const float* Wout = (const float*)d_in[5];
    const float* bout = (const float*)d_in[6];
    float*       out  = (float*)d_out;

    float *qkv_ptr, *ao_ptr;
    cudaGetSymbolAddress((void**)&qkv_ptr, g_qkv);
    cudaGetSymbolAddress((void**)&ao_ptr,  g_ao);

    // 1) QKV projection: (16384 x 1024) @ (1024 x 3072) + bias
    sgemm_bias<<<dim3(QKVDIM / 128, MROWS / 128), 256>>>(
        x, Wqkv, bqkv, qkv_ptr, MROWS, QKVDIM, DIMSZ);

    // 2) low-rank K/V projections
    lowrank_proj<<<dim3(BATCH * NHEAD, 2), 256>>>(E, F);

    // 3) fused attention
    attn_kernel<<<dim3(NSEQ / 16, BATCH * NHEAD), 512>>>();

    // 4) output projection: (16384 x 1024) @ (1024 x 1024) + bias
    sgemm_bias<<<dim3(DIMSZ / 128, MROWS / 128), 256>>>(
        ao_ptr, Wout, bout, out, MROWS, DIMSZ, DIMSZ);
}

// round 6
// speedup vs baseline: 3.2095x; 3.2095x over previous
#include <cuda_runtime.h>
#include <cuda_bf16.h>
#include <cstdint>
#include <cstddef>

#define NSEQ   4096
#define BATCH  4
#define DIMSZ  1024
#define NHEAD  16
#define KLR    64
#define DH     64
#define MROWS  (NSEQ*BATCH)     /* 16384 */
#define QKVDIM (3*DIMSZ)        /* 3072  */

// ---------------- scratch (static device globals; no allocation) -------------
__device__ float g_qkv[(size_t)MROWS * QKVDIM];            // fp32 QKV (201 MB)
__device__ float g_kp [BATCH*NHEAD*KLR*DH];
__device__ float g_vp [BATCH*NHEAD*KLR*DH];
__device__ __nv_bfloat16 g_xh [(size_t)MROWS * DIMSZ];     // x split
__device__ __nv_bfloat16 g_xl [(size_t)MROWS * DIMSZ];
__device__ __nv_bfloat16 g_wqh[(size_t)QKVDIM * DIMSZ];    // W_qkv^T split
__device__ __nv_bfloat16 g_wql[(size_t)QKVDIM * DIMSZ];
__device__ __nv_bfloat16 g_woh[(size_t)DIMSZ * DIMSZ];     // W_out^T split
__device__ __nv_bfloat16 g_wol[(size_t)DIMSZ * DIMSZ];
__device__ __nv_bfloat16 g_aoh[(size_t)MROWS * DIMSZ];     // attn out split
__device__ __nv_bfloat16 g_aol[(size_t)MROWS * DIMSZ];

// ============================ small helpers ==================================
__device__ __forceinline__ uint32_t smem_u32(const void* p) {
    uint32_t a;
    asm("{ .reg .u64 t; cvta.to.shared.u64 t, %1; cvt.u32.u64 %0, t; }"
        : "=r"(a) : "l"(p));
    return a;
}
__device__ __forceinline__ uint32_t sw128(uint32_t off) {
    return off ^ ((off >> 3) & 0x70);
}
__device__ __forceinline__ void cp16(uint32_t dst, const void* src) {
    asm volatile("cp.async.cg.shared.global [%0], [%1], 16;"
                 :: "r"(dst), "l"(src));
}
__device__ __forceinline__ void ldsm4(uint32_t* r, uint32_t addr) {
    asm volatile("ldmatrix.sync.aligned.m8n8.x4.shared.b16 {%0,%1,%2,%3}, [%4];"
                 : "=r"(r[0]), "=r"(r[1]), "=r"(r[2]), "=r"(r[3]) : "r"(addr));
}
__device__ __forceinline__ void mma16816(float* c, const uint32_t* a,
                                         uint32_t b0, uint32_t b1) {
    asm volatile(
        "mma.sync.aligned.m16n8k16.row.col.f32.bf16.bf16.f32 "
        "{%0,%1,%2,%3}, {%4,%5,%6,%7}, {%8,%9}, {%0,%1,%2,%3};"
        : "+f"(c[0]), "+f"(c[1]), "+f"(c[2]), "+f"(c[3])
        : "r"(a[0]), "r"(a[1]), "r"(a[2]), "r"(a[3]), "r"(b0), "r"(b1));
}

// ========== HMMA GEMM: C = A(MxK) @ B^T(NxK) + bias, fp32-split bf16 =========
// A given as hi/lo bf16 [M][K]; B given TRANSPOSED hi/lo bf16 [N][K].
// CTA 128x128, BK=64, 3-stage cp.async pipeline, 8 warps (4m x 2n).
#define STAGES      3
#define STAGE_BYTES 65536
#define GEMM_SMEM   (STAGES * STAGE_BYTES)

__global__ __launch_bounds__(256) void gemm_bf16s(
    const __nv_bfloat16* __restrict__ Ah, const __nv_bfloat16* __restrict__ Al,
    const __nv_bfloat16* __restrict__ Bh, const __nv_bfloat16* __restrict__ Bl,
    const float* __restrict__ bias, float* __restrict__ C,
    int M, int N, int K)
{
    extern __shared__ __align__(1024) char smem[];
    const uint32_t sb  = smem_u32(smem);
    const int tid  = threadIdx.x;
    const int lane = tid & 31;
    const int wid  = tid >> 5;
    const int wm   = wid >> 1;          // 0..3 -> m offset wm*32
    const int wn   = wid & 1;           // 0..1 -> n offset wn*64
    const int bm0  = blockIdx.y * 128;
    const int bn0  = blockIdx.x * 128;
    const int niter = K / 64;

    float acc[2][8][4] = {};

    // ---- stage loader: 4096 x 16B chunks (Ah|Al|Bh|Bl tiles), SW128 swizzle
    auto load_stage = [&](int stage, int it) {
        const uint32_t base = sb + stage * STAGE_BYTES;
        const int k0 = it * 64;
        #pragma unroll
        for (int u = 0; u < 16; u++) {
            int idx  = u * 256 + tid;
            int comp = u >> 2;                 // == idx >> 10
            int rem  = idx & 1023;
            int r    = rem >> 3;
            int j    = rem & 7;
            const __nv_bfloat16* p =
                comp == 0 ? Ah : comp == 1 ? Al : comp == 2 ? Bh : Bl;
            int rb = (comp < 2) ? bm0 : bn0;
            uint32_t dst = base + comp * 16384 + sw128((uint32_t)(r * 128 + j * 16));
            cp16(dst, p + (size_t)(rb + r) * K + k0 + j * 8);
        }
    };

    // prologue: stages 0,1
    load_stage(0, 0);
    asm volatile("cp.async.commit_group;" ::: "memory");
    if (niter > 1) load_stage(1, 1);
    asm volatile("cp.async.commit_group;" ::: "memory");

    for (int it = 0; it < niter; it++) {
        asm volatile("cp.async.wait_group 1;" ::: "memory");
        __syncthreads();

        int nx = it + 2;
        if (nx < niter) load_stage(nx % STAGES, nx);
        asm volatile("cp.async.commit_group;" ::: "memory");

        // ---- compute on stage it%STAGES
        const uint32_t st  = sb + (it % STAGES) * STAGE_BYTES;
        const uint32_t sAh = st, sAl = st + 16384, sBh = st + 32768, sBl = st + 49152;

        #pragma unroll
        for (int ks = 0; ks < 4; ks++) {
            uint32_t aH[2][4], aL[2][4], bH[4][4], bL[4][4];
            #pragma unroll
            for (int mi = 0; mi < 2; mi++) {
                int row = wm * 32 + mi * 16 + (lane & 15);
                int col = ks * 32 + ((lane & 16) ? 16 : 0);
                uint32_t off = sw128((uint32_t)(row * 128 + col));
                ldsm4(aH[mi], sAh + off);
                ldsm4(aL[mi], sAl + off);
            }
            #pragma unroll
            for (int ntp = 0; ntp < 4; ntp++) {
                int row = wn * 64 + ntp * 16 + (lane & 7) + ((lane & 16) ? 8 : 0);
                int col = ks * 32 + ((lane & 8) ? 16 : 0);
                uint32_t off = sw128((uint32_t)(row * 128 + col));
                ldsm4(bH[ntp], sBh + off);
                ldsm4(bL[ntp], sBl + off);
            }
            #pragma unroll
            for (int mi = 0; mi < 2; mi++) {
                #pragma unroll
                for (int ni = 0; ni < 8; ni++) {
                    uint32_t b0h = bH[ni >> 1][(ni & 1) * 2];
                    uint32_t b1h = bH[ni >> 1][(ni & 1) * 2 + 1];
                    uint32_t b0l = bL[ni >> 1][(ni & 1) * 2];
                    uint32_t b1l = bL[ni >> 1][(ni & 1) * 2 + 1];
                    mma16816(acc[mi][ni], aH[mi], b0h, b1h);
                    mma16816(acc[mi][ni], aH[mi], b0l, b1l);
                    mma16816(acc[mi][ni], aL[mi], b0h, b1h);
                }
            }
        }
    }

    // ---- epilogue: frag layout -> C with bias
    #pragma unroll
    for (int mi = 0; mi < 2; mi++) {
        #pragma unroll
        for (int ni = 0; ni < 8; ni++) {
            int row = bm0 + wm * 32 + mi * 16 + (lane >> 2);
            int col = bn0 + wn * 64 + ni * 8 + (lane & 3) * 2;
            float b0 = bias[col], b1 = bias[col + 1];
            float2 o0 = {acc[mi][ni][0] + b0, acc[mi][ni][1] + b1};
            float2 o1 = {acc[mi][ni][2] + b0, acc[mi][ni][3] + b1};
            *(float2*)(C + (size_t)row * N + col)       = o0;
            *(float2*)(C + (size_t)(row + 8) * N + col) = o1;
        }
    }
}

// ============== fp32 -> bf16 hi/lo element-wise split (x) ====================
__global__ __launch_bounds__(256) void split_f32(
    const float* __restrict__ in, __nv_bfloat16* __restrict__ oh,
    __nv_bfloat16* __restrict__ ol, int n4)
{
    int i = blockIdx.x * 256 + threadIdx.x;
    if (i >= n4) return;
    float4 v = ((const float4*)in)[i];
    float f[4] = {v.x, v.y, v.z, v.w};
    ushort4 uh, ul;
    unsigned short* ph = &uh.x;
    unsigned short* pl = &ul.x;
    #pragma unroll
    for (int j = 0; j < 4; j++) {
        __nv_bfloat16 h = __float2bfloat16(f[j]);
        __nv_bfloat16 l = __float2bfloat16(f[j] - __bfloat162float(h));
        ph[j] = __bfloat16_as_ushort(h);
        pl[j] = __bfloat16_as_ushort(l);
    }
    ((ushort4*)oh)[i] = uh;
    ((ushort4*)ol)[i] = ul;
}

// ============== W[K][N] -> W^T[N][K] bf16 hi/lo split ========================
__global__ __launch_bounds__(256) void transpose_split(
    const float* __restrict__ W, __nv_bfloat16* __restrict__ th,
    __nv_bfloat16* __restrict__ tl, int K, int N)
{
    __shared__ float t[32][33];
    const int tx = threadIdx.x, ty = threadIdx.y;
    const int n0 = blockIdx.x * 32, k0 = blockIdx.y * 32;
    #pragma unroll
    for (int i = 0; i < 4; i++)
        t[ty + i * 8][tx] = W[(size_t)(k0 + ty + i * 8) * N + n0 + tx];
    __syncthreads();
    #pragma unroll
    for (int i = 0; i < 4; i++) {
        int n = n0 + ty + i * 8, k = k0 + tx;
        float v = t[tx][ty + i * 8];
        __nv_bfloat16 h = __float2bfloat16(v);
        th[(size_t)n * K + k] = h;
        tl[(size_t)n * K + k] = __float2bfloat16(v - __bfloat162float(h));
    }
}

// ---------------- low-rank projection (fp32) ---------------------------------
__global__ __launch_bounds__(256) void lowrank_proj(
    const float* __restrict__ E, const float* __restrict__ F)
{
    const int bh    = blockIdx.x;
    const int which = blockIdx.y;
    const int b     = bh >> 4;
    const int h     = bh & 15;

    const float* P   = which ? F : E;
    const int    off = (which ? 2 * DIMSZ : DIMSZ) + h * DH;
    float*       out = (which ? g_vp : g_kp) + bh * KLR * DH;

    __shared__ float Ps[64][64];
    __shared__ float Ss[64][64];

    const int tid = threadIdx.x;
    const int ty  = tid >> 4;
    const int tx  = tid & 15;

    float acc[4][4];
    #pragma unroll
    for (int i = 0; i < 4; i++)
        #pragma unroll
        for (int j = 0; j < 4; j++) acc[i][j] = 0.f;

    for (int n0 = 0; n0 < NSEQ; n0 += 64) {
        #pragma unroll 4
        for (int idx = tid; idx < 4096; idx += 256) {
            int nn = idx >> 6, c = idx & 63;
            Ps[nn][c] = P[(size_t)(n0 + nn) * KLR + c];
            Ss[nn][c] = g_qkv[((size_t)(n0 + nn) * BATCH + b) * QKVDIM + off + c];
        }
        __syncthreads();
        #pragma unroll 8
        for (int nn = 0; nn < 64; nn++) {
            float4 p4 = *(const float4*)&Ps[nn][ty * 4];
            float4 s4 = *(const float4*)&Ss[nn][tx * 4];
            float p[4] = {p4.x, p4.y, p4.z, p4.w};
            float s[4] = {s4.x, s4.y, s4.z, s4.w};
            #pragma unroll
            for (int i = 0; i < 4; i++)
                #pragma unroll
                for (int j = 0; j < 4; j++)
                    acc[i][j] += p[i] * s[j];
        }
        __syncthreads();
    }

    #pragma unroll
    for (int i = 0; i < 4; i++) {
        int k = ty * 4 + i;
        float4 o = {acc[i][0], acc[i][1], acc[i][2], acc[i][3]};
        *(float4*)&out[k * DH + tx * 4] = o;
    }
}

// ---------------- fused attention; writes bf16 hi/lo ao ----------------------
__global__ __launch_bounds__(512) void attn_kernel()
{
    const int bh = blockIdx.y;
    const int b  = bh >> 4;
    const int h  = bh & 15;
    const int n0 = blockIdx.x * 16;

    __shared__ float KpT[DH][KLR + 1];
    __shared__ float Vs [KLR][DH];
    __shared__ float qs [16][DH];
    __shared__ float as [16][KLR];

    const int tid = threadIdx.x;
    const float* Kp = g_kp + bh * KLR * DH;
    const float* Vp = g_vp + bh * KLR * DH;

    for (int idx = tid; idx < KLR * DH; idx += 512) {
        int k = idx >> 6, d = idx & 63;
        KpT[d][k] = Kp[idx];
        Vs[k][d]  = Vp[idx];
    }
    for (int idx = tid; idx < 16 * DH; idx += 512) {
        int r = idx >> 6, d = idx & 63;
        qs[r][d] = g_qkv[((size_t)(n0 + r) * BATCH + b) * QKVDIM + h * DH + d];
    }
    __syncthreads();

    const int w = tid >> 5;
    const int l = tid & 31;

    float a0 = 0.f, a1 = 0.f;
    #pragma unroll
    for (int d = 0; d < DH; d++) {
        float qv = qs[w][d];
        a0 += qv * KpT[d][l];
        a1 += qv * KpT[d][l + 32];
    }
    const float scale = 0.125f;
    a0 *= scale; a1 *= scale;

    float m = fmaxf(a0, a1);
    #pragma unroll
    for (int o = 16; o > 0; o >>= 1) m = fmaxf(m, __shfl_xor_sync(0xffffffffu, m, o));
    float e0 = __expf(a0 - m), e1 = __expf(a1 - m);
    float s = e0 + e1;
    #pragma unroll
    for (int o = 16; o > 0; o >>= 1) s += __shfl_xor_sync(0xffffffffu, s, o);
    float inv = 1.0f / s;
    as[w][l]      = e0 * inv;
    as[w][l + 32] = e1 * inv;
    __syncwarp();

    float o0 = 0.f, o1 = 0.f;
    #pragma unroll
    for (int k = 0; k < KLR; k++) {
        float av = as[w][k];
        o0 += av * Vs[k][l];
        o1 += av * Vs[k][l + 32];
    }
    size_t base = ((size_t)(n0 + w) * BATCH + b) * DIMSZ + h * DH;
    __nv_bfloat16 h0 = __float2bfloat16(o0);
    __nv_bfloat16 h1 = __float2bfloat16(o1);
    g_aoh[base + l]      = h0;
    g_aol[base + l]      = __float2bfloat16(o0 - __bfloat162float(h0));
    g_aoh[base + l + 32] = h1;
    g_aol[base + l + 32] = __float2bfloat16(o1 - __bfloat162float(h1));
}

// ---------------- launch -----------------------------------------------------
extern "C" void kernel_launch(void* const* d_in, const int* in_sizes, int n_in,
                              void* d_out, int out_size)
{
    const float* x    = (const float*)d_in[0];
    const float* E    = (const float*)d_in[1];
    const float* F    = (const float*)d_in[2];
    const float* Wqkv = (const float*)d_in[3];
    const float* bqkv = (const float*)d_in[4];
    const float* Wout = (const float*)d_in[5];
    const float* bout = (const float*)d_in[6];
    float*       out  = (float*)d_out;

    float *qkv_ptr;
    __nv_bfloat16 *xh, *xl, *wqh, *wql, *woh, *wol, *aoh, *aol;
    cudaGetSymbolAddress((void**)&qkv_ptr, g_qkv);
    cudaGetSymbolAddress((void**)&xh,  g_xh);
    cudaGetSymbolAddress((void**)&xl,  g_xl);
    cudaGetSymbolAddress((void**)&wqh, g_wqh);
    cudaGetSymbolAddress((void**)&wql, g_wql);
    cudaGetSymbolAddress((void**)&woh, g_woh);
    cudaGetSymbolAddress((void**)&wol, g_wol);
    cudaGetSymbolAddress((void**)&aoh, g_aoh);
    cudaGetSymbolAddress((void**)&aol, g_aol);

    cudaFuncSetAttribute(gemm_bf16s,
                         cudaFuncAttributeMaxDynamicSharedMemorySize, GEMM_SMEM);

    // 0) operand prep: split x; transpose+split weights
    split_f32<<<(MROWS * DIMSZ / 4 + 255) / 256, 256>>>(x, xh, xl, MROWS * DIMSZ / 4);
    transpose_split<<<dim3(QKVDIM / 32, DIMSZ / 32), dim3(32, 8)>>>(
        Wqkv, wqh, wql, DIMSZ, QKVDIM);
    transpose_split<<<dim3(DIMSZ / 32, DIMSZ / 32), dim3(32, 8)>>>(
        Wout, woh, wol, DIMSZ, DIMSZ);

    // 1) QKV projection: (16384 x 1024) @ (1024 x 3072) + bias   [HMMA]
    gemm_bf16s<<<dim3(QKVDIM / 128, MROWS / 128), 256, GEMM_SMEM>>>(
        xh, xl, wqh, wql, bqkv, qkv_ptr, MROWS, QKVDIM, DIMSZ);

    // 2) low-rank K/V projections
    lowrank_proj<<<dim3(BATCH * NHEAD, 2), 256>>>(E, F);

    // 3) fused attention (emits bf16 hi/lo ao)
    attn_kernel<<<dim3(NSEQ / 16, BATCH * NHEAD), 512>>>();

    // 4) output projection: (16384 x 1024) @ (1024 x 1024) + bias [HMMA]
    gemm_bf16s<<<dim3(DIMSZ / 128, MROWS / 128), 256, GEMM_SMEM>>>(
        aoh, aol, woh, wol, bout, out, MROWS, DIMSZ, DIMSZ);
}

// round 7
// speedup vs baseline: 3.8507x; 1.1998x over previous
#include <cuda_runtime.h>
#include <cuda_bf16.h>
#include <cstdint>
#include <cstddef>

#define NSEQ   4096
#define BATCH  4
#define DIMSZ  1024
#define NHEAD  16
#define KLR    64
#define DH     64
#define MROWS  (NSEQ*BATCH)     /* 16384 */
#define QKVDIM (3*DIMSZ)        /* 3072  */

// ---------------- scratch (static device globals; no allocation) -------------
__device__ float g_q  [(size_t)MROWS * DIMSZ];             // Q fp32 (67 MB)
__device__ float g_xe [(size_t)BATCH * KLR * DIMSZ];       // E^T x  (b,k,d)
__device__ float g_xf [(size_t)BATCH * KLR * DIMSZ];       // F^T x
__device__ float g_kp [(size_t)BATCH * KLR * DIMSZ];       // Kp (b,k, h*64+d)
__device__ float g_vp [(size_t)BATCH * KLR * DIMSZ];       // Vp
__device__ float g_sef[2 * KLR];                           // col sums of E, F
__device__ __nv_bfloat16 g_xh [(size_t)MROWS * DIMSZ];     // x split
__device__ __nv_bfloat16 g_xl [(size_t)MROWS * DIMSZ];
__device__ __nv_bfloat16 g_xeh[(size_t)BATCH * KLR * DIMSZ];
__device__ __nv_bfloat16 g_xel[(size_t)BATCH * KLR * DIMSZ];
__device__ __nv_bfloat16 g_xfh[(size_t)BATCH * KLR * DIMSZ];
__device__ __nv_bfloat16 g_xfl[(size_t)BATCH * KLR * DIMSZ];
__device__ __nv_bfloat16 g_wqh[(size_t)QKVDIM * DIMSZ];    // W_qkv^T split
__device__ __nv_bfloat16 g_wql[(size_t)QKVDIM * DIMSZ];
__device__ __nv_bfloat16 g_woh[(size_t)DIMSZ * DIMSZ];     // W_out^T split
__device__ __nv_bfloat16 g_wol[(size_t)DIMSZ * DIMSZ];
__device__ __nv_bfloat16 g_aoh[(size_t)MROWS * DIMSZ];     // attn out split
__device__ __nv_bfloat16 g_aol[(size_t)MROWS * DIMSZ];

// ============================ small helpers ==================================
__device__ __forceinline__ uint32_t smem_u32(const void* p) {
    uint32_t a;
    asm("{ .reg .u64 t; cvta.to.shared.u64 t, %1; cvt.u32.u64 %0, t; }"
        : "=r"(a) : "l"(p));
    return a;
}
__device__ __forceinline__ uint32_t sw128(uint32_t off) {
    return off ^ ((off >> 3) & 0x70);
}
__device__ __forceinline__ void cp16(uint32_t dst, const void* src) {
    asm volatile("cp.async.cg.shared.global [%0], [%1], 16;"
                 :: "r"(dst), "l"(src));
}
__device__ __forceinline__ void ldsm4(uint32_t* r, uint32_t addr) {
    asm volatile("ldmatrix.sync.aligned.m8n8.x4.shared.b16 {%0,%1,%2,%3}, [%4];"
                 : "=r"(r[0]), "=r"(r[1]), "=r"(r[2]), "=r"(r[3]) : "r"(addr));
}
__device__ __forceinline__ void mma16816(float* c, const uint32_t* a,
                                         uint32_t b0, uint32_t b1) {
    asm volatile(
        "mma.sync.aligned.m16n8k16.row.col.f32.bf16.bf16.f32 "
        "{%0,%1,%2,%3}, {%4,%5,%6,%7}, {%8,%9}, {%0,%1,%2,%3};"
        : "+f"(c[0]), "+f"(c[1]), "+f"(c[2]), "+f"(c[3])
        : "r"(a[0]), "r"(a[1]), "r"(a[2]), "r"(a[3]), "r"(b0), "r"(b1));
}

// ========== HMMA GEMM body: C = A(MxK)@B^T(NxK) + rs[row&63]*bias ===========
// A hi/lo bf16 [M][K]; B TRANSPOSED hi/lo bf16 [N][K]. CTA 128x128, BK=64,
// 3-stage cp.async pipeline, 8 warps (4m x 2n). rs==nullptr -> scale 1.
#define STAGES      3
#define STAGE_BYTES 65536
#define GEMM_SMEM   (STAGES * STAGE_BYTES)

__device__ __forceinline__ void gemm_body(
    const __nv_bfloat16* __restrict__ Ah, const __nv_bfloat16* __restrict__ Al,
    const __nv_bfloat16* __restrict__ Bh, const __nv_bfloat16* __restrict__ Bl,
    const float* __restrict__ bias, const float* __restrict__ rs,
    float* __restrict__ C, int N, int K, int bm0, int bn0)
{
    extern __shared__ __align__(1024) char smem[];
    const uint32_t sb  = smem_u32(smem);
    const int tid  = threadIdx.x;
    const int lane = tid & 31;
    const int wid  = tid >> 5;
    const int wm   = wid >> 1;
    const int wn   = wid & 1;
    const int niter = K / 64;

    float acc[2][8][4] = {};

    auto load_stage = [&](int stage, int it) {
        const uint32_t base = sb + stage * STAGE_BYTES;
        const int k0 = it * 64;
        #pragma unroll
        for (int u = 0; u < 16; u++) {
            int idx  = u * 256 + tid;
            int comp = u >> 2;
            int rem  = idx & 1023;
            int r    = rem >> 3;
            int j    = rem & 7;
            const __nv_bfloat16* p =
                comp == 0 ? Ah : comp == 1 ? Al : comp == 2 ? Bh : Bl;
            int rb = (comp < 2) ? bm0 : bn0;
            uint32_t dst = base + comp * 16384 + sw128((uint32_t)(r * 128 + j * 16));
            cp16(dst, p + (size_t)(rb + r) * K + k0 + j * 8);
        }
    };

    load_stage(0, 0);
    asm volatile("cp.async.commit_group;" ::: "memory");
    if (niter > 1) load_stage(1, 1);
    asm volatile("cp.async.commit_group;" ::: "memory");

    for (int it = 0; it < niter; it++) {
        asm volatile("cp.async.wait_group 1;" ::: "memory");
        __syncthreads();

        int nx = it + 2;
        if (nx < niter) load_stage(nx % STAGES, nx);
        asm volatile("cp.async.commit_group;" ::: "memory");

        const uint32_t st  = sb + (it % STAGES) * STAGE_BYTES;
        const uint32_t sAh = st, sAl = st + 16384, sBh = st + 32768, sBl = st + 49152;

        #pragma unroll
        for (int ks = 0; ks < 4; ks++) {
            uint32_t aH[2][4], aL[2][4], bH[4][4], bL[4][4];
            #pragma unroll
            for (int mi = 0; mi < 2; mi++) {
                int row = wm * 32 + mi * 16 + (lane & 15);
                int col = ks * 32 + ((lane & 16) ? 16 : 0);
                uint32_t off = sw128((uint32_t)(row * 128 + col));
                ldsm4(aH[mi], sAh + off);
                ldsm4(aL[mi], sAl + off);
            }
            #pragma unroll
            for (int ntp = 0; ntp < 4; ntp++) {
                int row = wn * 64 + ntp * 16 + (lane & 7) + ((lane & 16) ? 8 : 0);
                int col = ks * 32 + ((lane & 8) ? 16 : 0);
                uint32_t off = sw128((uint32_t)(row * 128 + col));
                ldsm4(bH[ntp], sBh + off);
                ldsm4(bL[ntp], sBl + off);
            }
            #pragma unroll
            for (int mi = 0; mi < 2; mi++) {
                #pragma unroll
                for (int ni = 0; ni < 8; ni++) {
                    uint32_t b0h = bH[ni >> 1][(ni & 1) * 2];
                    uint32_t b1h = bH[ni >> 1][(ni & 1) * 2 + 1];
                    uint32_t b0l = bL[ni >> 1][(ni & 1) * 2];
                    uint32_t b1l = bL[ni >> 1][(ni & 1) * 2 + 1];
                    mma16816(acc[mi][ni], aH[mi], b0h, b1h);
                    mma16816(acc[mi][ni], aH[mi], b0l, b1l);
                    mma16816(acc[mi][ni], aL[mi], b0h, b1h);
                }
            }
        }
    }

    #pragma unroll
    for (int mi = 0; mi < 2; mi++) {
        #pragma unroll
        for (int ni = 0; ni < 8; ni++) {
            int row = bm0 + wm * 32 + mi * 16 + (lane >> 2);
            int col = bn0 + wn * 64 + ni * 8 + (lane & 3) * 2;
            float s0 = rs ? rs[row & 63] : 1.0f;
            float s1 = rs ? rs[(row + 8) & 63] : 1.0f;
            float b0 = bias[col], b1 = bias[col + 1];
            float2 o0 = {acc[mi][ni][0] + s0 * b0, acc[mi][ni][1] + s0 * b1};
            float2 o1 = {acc[mi][ni][2] + s1 * b0, acc[mi][ni][3] + s1 * b1};
            *(float2*)(C + (size_t)row * N + col)       = o0;
            *(float2*)(C + (size_t)(row + 8) * N + col) = o1;
        }
    }
}

__global__ __launch_bounds__(256) void gemm_bf16s(
    const __nv_bfloat16* __restrict__ Ah, const __nv_bfloat16* __restrict__ Al,
    const __nv_bfloat16* __restrict__ Bh, const __nv_bfloat16* __restrict__ Bl,
    const float* __restrict__ bias, float* __restrict__ C, int N, int K)
{
    gemm_body(Ah, Al, Bh, Bl, bias, nullptr, C, N, K,
              blockIdx.y * 128, blockIdx.x * 128);
}

// Kp/Vp GEMM: z=0 -> Kp = xE @ Wk + sE*bk ; z=1 -> Vp = xF @ Wv + sF*bv
__global__ __launch_bounds__(256) void gemm_kpvp()
{
    const int which = blockIdx.z;
    const __nv_bfloat16* Ah = which ? g_xfh : g_xeh;
    const __nv_bfloat16* Al = which ? g_xfl : g_xel;
    const __nv_bfloat16* Bh = g_wqh + (size_t)(which + 1) * DIMSZ * DIMSZ;
    const __nv_bfloat16* Bl = g_wql + (size_t)(which + 1) * DIMSZ * DIMSZ;
    float* C = which ? g_vp : g_kp;
    gemm_body(Ah, Al, Bh, Bl, nullptr, g_sef + which * KLR, C, DIMSZ, DIMSZ,
              blockIdx.y * 128, blockIdx.x * 128);
}
// bias passed via constant path: gemm_kpvp needs the b_qkv slice; store it:
__device__ float g_bk[2 * DIMSZ];   // [0]=b_k slice, [1]=b_v slice

__global__ __launch_bounds__(256) void gemm_kpvp2(const float* __restrict__ bqkv)
{
    const int which = blockIdx.z;
    const __nv_bfloat16* Ah = which ? g_xfh : g_xeh;
    const __nv_bfloat16* Al = which ? g_xfl : g_xel;
    const __nv_bfloat16* Bh = g_wqh + (size_t)(which + 1) * DIMSZ * DIMSZ;
    const __nv_bfloat16* Bl = g_wql + (size_t)(which + 1) * DIMSZ * DIMSZ;
    float* C = which ? g_vp : g_kp;
    gemm_body(Ah, Al, Bh, Bl, bqkv + (which + 1) * DIMSZ,
              g_sef + which * KLR, C, DIMSZ, DIMSZ,
              blockIdx.y * 128, blockIdx.x * 128);
}

// ============== fp32 -> bf16 hi/lo element-wise split ========================
__global__ __launch_bounds__(256) void split_f32(
    const float* __restrict__ in, __nv_bfloat16* __restrict__ oh,
    __nv_bfloat16* __restrict__ ol, int n4)
{
    int i = blockIdx.x * 256 + threadIdx.x;
    if (i >= n4) return;
    float4 v = ((const float4*)in)[i];
    float f[4] = {v.x, v.y, v.z, v.w};
    ushort4 uh, ul;
    unsigned short* ph = &uh.x;
    unsigned short* pl = &ul.x;
    #pragma unroll
    for (int j = 0; j < 4; j++) {
        __nv_bfloat16 h = __float2bfloat16(f[j]);
        __nv_bfloat16 l = __float2bfloat16(f[j] - __bfloat162float(h));
        ph[j] = __bfloat16_as_ushort(h);
        pl[j] = __bfloat16_as_ushort(l);
    }
    ((ushort4*)oh)[i] = uh;
    ((ushort4*)ol)[i] = ul;
}

// ============== W[K][N] -> W^T[N][K] bf16 hi/lo split ========================
__global__ __launch_bounds__(256) void transpose_split(
    const float* __restrict__ W, __nv_bfloat16* __restrict__ th,
    __nv_bfloat16* __restrict__ tl, int K, int N)
{
    __shared__ float t[32][33];
    const int tx = threadIdx.x, ty = threadIdx.y;
    const int n0 = blockIdx.x * 32, k0 = blockIdx.y * 32;
    #pragma unroll
    for (int i = 0; i < 4; i++)
        t[ty + i * 8][tx] = W[(size_t)(k0 + ty + i * 8) * N + n0 + tx];
    __syncthreads();
    #pragma unroll
    for (int i = 0; i < 4; i++) {
        int n = n0 + ty + i * 8, k = k0 + tx;
        float v = t[tx][ty + i * 8];
        __nv_bfloat16 h = __float2bfloat16(v);
        th[(size_t)n * K + k] = h;
        tl[(size_t)n * K + k] = __float2bfloat16(v - __bfloat162float(h));
    }
}

// ============== column sums of E and F: g_sef[which][k] ======================
__global__ __launch_bounds__(256) void colsum(const float* __restrict__ E,
                                              const float* __restrict__ F)
{
    const int which = blockIdx.x;
    const float* P = which ? F : E;
    const int k = threadIdx.x & 63;
    const int g = threadIdx.x >> 6;
    float s = 0.f;
    for (int i = 0; i < NSEQ / 4; i++)
        s += P[(size_t)(g * (NSEQ / 4) + i) * KLR + k];
    __shared__ float red[4][64];
    red[g][k] = s;
    __syncthreads();
    if (g == 0)
        g_sef[which * KLR + k] = red[0][k] + red[1][k] + red[2][k] + red[3][k];
}

// ============== xEF: out[b][kl][d] = sum_n P[n][kl] * x[n][b][d] =============
// grid (16 d-tiles, 4 b, 2 which), 256 threads, 64x64 tile, fp32.
__global__ __launch_bounds__(256) void xef_kernel(
    const float* __restrict__ x, const float* __restrict__ E,
    const float* __restrict__ F)
{
    const int dt    = blockIdx.x;
    const int b     = blockIdx.y;
    const int which = blockIdx.z;
    const float* P  = which ? F : E;
    float*       out = (which ? g_xf : g_xe) + (size_t)b * KLR * DIMSZ + dt * 64;

    __shared__ float Ps[64][64];
    __shared__ float Ss[64][65];

    const int tid = threadIdx.x;
    const int ty  = tid >> 4;
    const int tx  = tid & 15;

    float acc[4][4] = {};

    for (int n0 = 0; n0 < NSEQ; n0 += 64) {
        #pragma unroll 4
        for (int idx = tid; idx < 4096; idx += 256) {
            int nn = idx >> 6, c = idx & 63;
            Ps[nn][c] = P[(size_t)(n0 + nn) * KLR + c];
            Ss[nn][c] = x[((size_t)(n0 + nn) * BATCH + b) * DIMSZ + dt * 64 + c];
        }
        __syncthreads();
        #pragma unroll 8
        for (int nn = 0; nn < 64; nn++) {
            float4 p4 = *(const float4*)&Ps[nn][ty * 4];
            float s0 = Ss[nn][tx * 4 + 0], s1 = Ss[nn][tx * 4 + 1];
            float s2 = Ss[nn][tx * 4 + 2], s3 = Ss[nn][tx * 4 + 3];
            float p[4] = {p4.x, p4.y, p4.z, p4.w};
            float s[4] = {s0, s1, s2, s3};
            #pragma unroll
            for (int i = 0; i < 4; i++)
                #pragma unroll
                for (int j = 0; j < 4; j++)
                    acc[i][j] += p[i] * s[j];
        }
        __syncthreads();
    }

    #pragma unroll
    for (int i = 0; i < 4; i++) {
        int kl = ty * 4 + i;
        float4 o = {acc[i][0], acc[i][1], acc[i][2], acc[i][3]};
        *(float4*)&out[(size_t)kl * DIMSZ + tx * 4] = o;
    }
}

// ---------------- fused attention; writes bf16 hi/lo ao ----------------------
__global__ __launch_bounds__(512) void attn_kernel()
{
    const int bh = blockIdx.y;
    const int b  = bh >> 4;
    const int h  = bh & 15;
    const int n0 = blockIdx.x * 16;

    __shared__ float KpT[DH][KLR + 1];
    __shared__ float Vs [KLR][DH];
    __shared__ float qs [16][DH];
    __shared__ float as [16][KLR];

    const int tid = threadIdx.x;
    // Kp/Vp layout: [b][kl][h*64+d]
    const float* Kp = g_kp + (size_t)b * KLR * DIMSZ + h * DH;
    const float* Vp = g_vp + (size_t)b * KLR * DIMSZ + h * DH;

    for (int idx = tid; idx < KLR * DH; idx += 512) {
        int k = idx >> 6, d = idx & 63;
        KpT[d][k] = Kp[(size_t)k * DIMSZ + d];
        Vs[k][d]  = Vp[(size_t)k * DIMSZ + d];
    }
    for (int idx = tid; idx < 16 * DH; idx += 512) {
        int r = idx >> 6, d = idx & 63;
        qs[r][d] = g_q[((size_t)(n0 + r) * BATCH + b) * DIMSZ + h * DH + d];
    }
    __syncthreads();

    const int w = tid >> 5;
    const int l = tid & 31;

    float a0 = 0.f, a1 = 0.f;
    #pragma unroll
    for (int d = 0; d < DH; d++) {
        float qv = qs[w][d];
        a0 += qv * KpT[d][l];
        a1 += qv * KpT[d][l + 32];
    }
    const float scale = 0.125f;
    a0 *= scale; a1 *= scale;

    float m = fmaxf(a0, a1);
    #pragma unroll
    for (int o = 16; o > 0; o >>= 1) m = fmaxf(m, __shfl_xor_sync(0xffffffffu, m, o));
    float e0 = __expf(a0 - m), e1 = __expf(a1 - m);
    float s = e0 + e1;
    #pragma unroll
    for (int o = 16; o > 0; o >>= 1) s += __shfl_xor_sync(0xffffffffu, s, o);
    float inv = 1.0f / s;
    as[w][l]      = e0 * inv;
    as[w][l + 32] = e1 * inv;
    __syncwarp();

    float o0 = 0.f, o1 = 0.f;
    #pragma unroll
    for (int k = 0; k < KLR; k++) {
        float av = as[w][k];
        o0 += av * Vs[k][l];
        o1 += av * Vs[k][l + 32];
    }
    size_t base = ((size_t)(n0 + w) * BATCH + b) * DIMSZ + h * DH;
    __nv_bfloat16 h0 = __float2bfloat16(o0);
    __nv_bfloat16 h1 = __float2bfloat16(o1);
    g_aoh[base + l]      = h0;
    g_aol[base + l]      = __float2bfloat16(o0 - __bfloat162float(h0));
    g_aoh[base + l + 32] = h1;
    g_aol[base + l + 32] = __float2bfloat16(o1 - __bfloat162float(h1));
}

// ---------------- launch -----------------------------------------------------
extern "C" void kernel_launch(void* const* d_in, const int* in_sizes, int n_in,
                              void* d_out, int out_size)
{
    const float* x    = (const float*)d_in[0];
    const float* E    = (const float*)d_in[1];
    const float* F    = (const float*)d_in[2];
    const float* Wqkv = (const float*)d_in[3];
    const float* bqkv = (const float*)d_in[4];
    const float* Wout = (const float*)d_in[5];
    const float* bout = (const float*)d_in[6];
    float*       out  = (float*)d_out;

    float *qp, *xe, *xf;
    __nv_bfloat16 *xh, *xl, *xeh, *xel, *xfh, *xfl, *wqh, *wql, *woh, *wol,
                  *aoh, *aol;
    cudaGetSymbolAddress((void**)&qp,  g_q);
    cudaGetSymbolAddress((void**)&xe,  g_xe);
    cudaGetSymbolAddress((void**)&xf,  g_xf);
    cudaGetSymbolAddress((void**)&xh,  g_xh);
    cudaGetSymbolAddress((void**)&xl,  g_xl);
    cudaGetSymbolAddress((void**)&xeh, g_xeh);
    cudaGetSymbolAddress((void**)&xel, g_xel);
    cudaGetSymbolAddress((void**)&xfh, g_xfh);
    cudaGetSymbolAddress((void**)&xfl, g_xfl);
    cudaGetSymbolAddress((void**)&wqh, g_wqh);
    cudaGetSymbolAddress((void**)&wql, g_wql);
    cudaGetSymbolAddress((void**)&woh, g_woh);
    cudaGetSymbolAddress((void**)&wol, g_wol);
    cudaGetSymbolAddress((void**)&aoh, g_aoh);
    cudaGetSymbolAddress((void**)&aol, g_aol);

    cudaFuncSetAttribute(gemm_bf16s,
                         cudaFuncAttributeMaxDynamicSharedMemorySize, GEMM_SMEM);
    cudaFuncSetAttribute(gemm_kpvp2,
                         cudaFuncAttributeMaxDynamicSharedMemorySize, GEMM_SMEM);

    // 0) prep: split x; transpose+split weights; column sums of E/F
    split_f32<<<(MROWS * DIMSZ / 4 + 255) / 256, 256>>>(x, xh, xl,
                                                        MROWS * DIMSZ / 4);
    transpose_split<<<dim3(QKVDIM / 32, DIMSZ / 32), dim3(32, 8)>>>(
        Wqkv, wqh, wql, DIMSZ, QKVDIM);
    transpose_split<<<dim3(DIMSZ / 32, DIMSZ / 32), dim3(32, 8)>>>(
        Wout, woh, wol, DIMSZ, DIMSZ);
    colsum<<<2, 256>>>(E, F);

    // 1) xE = E^T x, xF = F^T x   (fp32, contraction over n)
    xef_kernel<<<dim3(DIMSZ / 64, BATCH, 2), 256>>>(x, E, F);
    split_f32<<<(BATCH * KLR * DIMSZ / 4 + 255) / 256, 256>>>(
        xe, xeh, xel, BATCH * KLR * DIMSZ / 4);
    split_f32<<<(BATCH * KLR * DIMSZ / 4 + 255) / 256, 256>>>(
        xf, xfh, xfl, BATCH * KLR * DIMSZ / 4);

    // 2) Q = x @ Wq + bq    [HMMA, 16384x1024x1024]
    gemm_bf16s<<<dim3(DIMSZ / 128, MROWS / 128), 256, GEMM_SMEM>>>(
        xh, xl, wqh, wql, bqkv, qp, DIMSZ, DIMSZ);

    // 3) Kp = xE @ Wk + sE*bk ; Vp = xF @ Wv + sF*bv   [HMMA, 256x1024x1024]
    gemm_kpvp2<<<dim3(DIMSZ / 128, (BATCH * KLR) / 128, 2), 256, GEMM_SMEM>>>(
        bqkv);

    // 4) fused attention (emits bf16 hi/lo ao)
    attn_kernel<<<dim3(NSEQ / 16, BATCH * NHEAD), 512>>>();

    // 5) output projection: (16384 x 1024) @ (1024 x 1024) + bias [HMMA]
    gemm_bf16s<<<dim3(DIMSZ / 128, MROWS / 128), 256, GEMM_SMEM>>>(
        aoh, aol, woh, wol, bout, out, DIMSZ, DIMSZ);
}

// round 9
// speedup vs baseline: 6.7666x; 1.7572x over previous
#include <cuda_runtime.h>
#include <cuda_bf16.h>
#include <cstdint>
#include <cstddef>

#define NSEQ   4096
#define BATCH  4
#define DIMSZ  1024
#define NHEAD  16
#define KLR    64
#define DH     64
#define MROWS  (NSEQ*BATCH)     /* 16384 */
#define QKVDIM (3*DIMSZ)        /* 3072  */

// ---------------- scratch (static device globals; no allocation) -------------
__device__ float g_sef[2 * KLR];                           // col sums of E, F
__device__ __nv_bfloat16 g_xh [(size_t)MROWS * DIMSZ];     // x split
__device__ __nv_bfloat16 g_xl [(size_t)MROWS * DIMSZ];
__device__ __nv_bfloat16 g_xth[(size_t)MROWS * DIMSZ];     // x^T [(b,d)][n]
__device__ __nv_bfloat16 g_xtl[(size_t)MROWS * DIMSZ];
__device__ __nv_bfloat16 g_efh[128 * NSEQ];                // [E^T;F^T] stacked
__device__ __nv_bfloat16 g_efl[128 * NSEQ];
__device__ __nv_bfloat16 g_xeh[(size_t)BATCH * KLR * DIMSZ];
__device__ __nv_bfloat16 g_xel[(size_t)BATCH * KLR * DIMSZ];
__device__ __nv_bfloat16 g_xfh[(size_t)BATCH * KLR * DIMSZ];
__device__ __nv_bfloat16 g_xfl[(size_t)BATCH * KLR * DIMSZ];
__device__ __nv_bfloat16 g_wqh[(size_t)QKVDIM * DIMSZ];    // W_qkv^T split
__device__ __nv_bfloat16 g_wql[(size_t)QKVDIM * DIMSZ];
__device__ __nv_bfloat16 g_woh[(size_t)DIMSZ * DIMSZ];     // W_out^T split
__device__ __nv_bfloat16 g_wol[(size_t)DIMSZ * DIMSZ];
__device__ __nv_bfloat16 g_qh [(size_t)MROWS * DIMSZ];     // Q split [(n,b)][d]
__device__ __nv_bfloat16 g_ql [(size_t)MROWS * DIMSZ];
__device__ __nv_bfloat16 g_kph[(size_t)BATCH * KLR * DIMSZ]; // Kp [b*64+kl][h*64+d]
__device__ __nv_bfloat16 g_kpl[(size_t)BATCH * KLR * DIMSZ];
__device__ __nv_bfloat16 g_vth[(size_t)BATCH * NHEAD * DH * KLR]; // V^T [bh][d][k]
__device__ __nv_bfloat16 g_vtl[(size_t)BATCH * NHEAD * DH * KLR];
__device__ __nv_bfloat16 g_aoh[(size_t)MROWS * DIMSZ];     // attn out split
__device__ __nv_bfloat16 g_aol[(size_t)MROWS * DIMSZ];

// ============================ small helpers ==================================
__device__ __forceinline__ uint32_t smem_u32(const void* p) {
    uint32_t a;
    asm("{ .reg .u64 t; cvta.to.shared.u64 t, %1; cvt.u32.u64 %0, t; }"
        : "=r"(a) : "l"(p));
    return a;
}
__device__ __forceinline__ uint32_t sw128(uint32_t off) {
    return off ^ ((off >> 3) & 0x70);
}
__device__ __forceinline__ void cp16(uint32_t dst, const void* src) {
    asm volatile("cp.async.cg.shared.global [%0], [%1], 16;"
                 :: "r"(dst), "l"(src));
}
__device__ __forceinline__ void ldsm4(uint32_t* r, uint32_t addr) {
    asm volatile("ldmatrix.sync.aligned.m8n8.x4.shared.b16 {%0,%1,%2,%3}, [%4];"
                 : "=r"(r[0]), "=r"(r[1]), "=r"(r[2]), "=r"(r[3]) : "r"(addr));
}
__device__ __forceinline__ void mma16816(float* c, const uint32_t* a,
                                         uint32_t b0, uint32_t b1) {
    asm volatile(
        "mma.sync.aligned.m16n8k16.row.col.f32.bf16.bf16.f32 "
        "{%0,%1,%2,%3}, {%4,%5,%6,%7}, {%8,%9}, {%0,%1,%2,%3};"
        : "+f"(c[0]), "+f"(c[1]), "+f"(c[2]), "+f"(c[3])
        : "r"(a[0]), "r"(a[1]), "r"(a[2]), "r"(a[3]), "r"(b0), "r"(b1));
}
__device__ __forceinline__ uint32_t pack_bf16_pair(float x, float y,
                                                   uint32_t& lo_out) {
    __nv_bfloat16 hx = __float2bfloat16(x);
    __nv_bfloat16 hy = __float2bfloat16(y);
    __nv_bfloat16 lx = __float2bfloat16(x - __bfloat162float(hx));
    __nv_bfloat16 ly = __float2bfloat16(y - __bfloat162float(hy));
    lo_out = (uint32_t)__bfloat16_as_ushort(lx) |
             ((uint32_t)__bfloat16_as_ushort(ly) << 16);
    return (uint32_t)__bfloat16_as_ushort(hx) |
           ((uint32_t)__bfloat16_as_ushort(hy) << 16);
}
__device__ __forceinline__ void store_split2(__nv_bfloat16* oh, __nv_bfloat16* ol,
                                             size_t idx, float v0, float v1) {
    uint32_t lo, hi = pack_bf16_pair(v0, v1, lo);
    *(uint32_t*)(oh + idx) = hi;
    *(uint32_t*)(ol + idx) = lo;
}

// ========== HMMA GEMM body: C = A(MxK)@B^T(NxK); fp32-split bf16 =============
// MODE 0: fp32 C = acc + bias[col]
// MODE 1: KV: v = acc + rs[row&63]*bias[col]; which==0 -> kph/kpl row-major,
//         which==1 -> vth/vtl transposed per-head [bh][d][k]
// MODE 2: Q: v = acc + bias[col]; split -> Oh/Ol row-major
// MODE 3: XEF: v = acc; row>>6 selects xe/xf; scatter [(b,kl)][d] splits
#define STAGES      3
#define STAGE_BYTES 65536
#define GEMM_SMEM   (STAGES * STAGE_BYTES)

template <int MODE>
__device__ __forceinline__ void gemm_body(
    const __nv_bfloat16* __restrict__ Ah, const __nv_bfloat16* __restrict__ Al,
    const __nv_bfloat16* __restrict__ Bh, const __nv_bfloat16* __restrict__ Bl,
    const float* __restrict__ bias, const float* __restrict__ rs,
    float* __restrict__ Cf, __nv_bfloat16* __restrict__ Oh,
    __nv_bfloat16* __restrict__ Ol, int N, int K, int bm0, int bn0, int which)
{
    extern __shared__ __align__(1024) char smem[];
    const uint32_t sb  = smem_u32(smem);
    const int tid  = threadIdx.x;
    const int lane = tid & 31;
    const int wid  = tid >> 5;
    const int wm   = wid >> 1;
    const int wn   = wid & 1;
    const int niter = K / 64;

    float acc[2][8][4] = {};

    auto load_stage = [&](int stage, int it) {
        const uint32_t base = sb + stage * STAGE_BYTES;
        const int k0 = it * 64;
        #pragma unroll
        for (int u = 0; u < 16; u++) {
            int idx  = u * 256 + tid;
            int comp = u >> 2;
            int rem  = idx & 1023;
            int r    = rem >> 3;
            int j    = rem & 7;
            const __nv_bfloat16* p =
                comp == 0 ? Ah : comp == 1 ? Al : comp == 2 ? Bh : Bl;
            int rb = (comp < 2) ? bm0 : bn0;
            uint32_t dst = base + comp * 16384 + sw128((uint32_t)(r * 128 + j * 16));
            cp16(dst, p + (size_t)(rb + r) * K + k0 + j * 8);
        }
    };

    load_stage(0, 0);
    asm volatile("cp.async.commit_group;" ::: "memory");
    if (niter > 1) load_stage(1, 1);
    asm volatile("cp.async.commit_group;" ::: "memory");

    for (int it = 0; it < niter; it++) {
        asm volatile("cp.async.wait_group 1;" ::: "memory");
        __syncthreads();

        int nx = it + 2;
        if (nx < niter) load_stage(nx % STAGES, nx);
        asm volatile("cp.async.commit_group;" ::: "memory");

        const uint32_t st  = sb + (it % STAGES) * STAGE_BYTES;
        const uint32_t sAh = st, sAl = st + 16384, sBh = st + 32768, sBl = st + 49152;

        #pragma unroll
        for (int ks = 0; ks < 4; ks++) {
            uint32_t aH[2][4], aL[2][4], bH[4][4], bL[4][4];
            #pragma unroll
            for (int mi = 0; mi < 2; mi++) {
                int row = wm * 32 + mi * 16 + (lane & 15);
                int col = ks * 32 + ((lane & 16) ? 16 : 0);
                uint32_t off = sw128((uint32_t)(row * 128 + col));
                ldsm4(aH[mi], sAh + off);
                ldsm4(aL[mi], sAl + off);
            }
            #pragma unroll
            for (int ntp = 0; ntp < 4; ntp++) {
                int row = wn * 64 + ntp * 16 + (lane & 7) + ((lane & 16) ? 8 : 0);
                int col = ks * 32 + ((lane & 8) ? 16 : 0);
                uint32_t off = sw128((uint32_t)(row * 128 + col));
                ldsm4(bH[ntp], sBh + off);
                ldsm4(bL[ntp], sBl + off);
            }
            #pragma unroll
            for (int mi = 0; mi < 2; mi++) {
                #pragma unroll
                for (int ni = 0; ni < 8; ni++) {
                    uint32_t b0h = bH[ni >> 1][(ni & 1) * 2];
                    uint32_t b1h = bH[ni >> 1][(ni & 1) * 2 + 1];
                    uint32_t b0l = bL[ni >> 1][(ni & 1) * 2];
                    uint32_t b1l = bL[ni >> 1][(ni & 1) * 2 + 1];
                    mma16816(acc[mi][ni], aH[mi], b0h, b1h);
                    mma16816(acc[mi][ni], aH[mi], b0l, b1l);
                    mma16816(acc[mi][ni], aL[mi], b0h, b1h);
                }
            }
        }
    }

    #pragma unroll
    for (int mi = 0; mi < 2; mi++) {
        #pragma unroll
        for (int ni = 0; ni < 8; ni++) {
            int row = bm0 + wm * 32 + mi * 16 + (lane >> 2);
            int col = bn0 + wn * 64 + ni * 8 + (lane & 3) * 2;
            #pragma unroll
            for (int half = 0; half < 2; half++) {
                int r  = row + half * 8;
                float v0 = acc[mi][ni][half * 2 + 0];
                float v1 = acc[mi][ni][half * 2 + 1];
                if (MODE == 0) {
                    float2 o = {v0 + bias[col], v1 + bias[col + 1]};
                    *(float2*)(Cf + (size_t)r * N + col) = o;
                } else if (MODE == 2) {
                    store_split2(Oh, Ol, (size_t)r * N + col,
                                 v0 + bias[col], v1 + bias[col + 1]);
                } else if (MODE == 1) {
                    float s = rs[r & 63];
                    float w0 = v0 + s * bias[col], w1 = v1 + s * bias[col + 1];
                    if (which == 0) {
                        store_split2(Oh, Ol, (size_t)r * N + col, w0, w1);
                    } else {
                        // vt[((b*16+h)*64 + d)*64 + kl], row=b*64+kl, col=h*64+d
                        int b2 = r >> 6, kl = r & 63, hh = col >> 6, d = col & 63;
                        size_t i0 = (((size_t)(b2 * 16 + hh) * 64) + d) * 64 + kl;
                        __nv_bfloat16 h0 = __float2bfloat16(w0);
                        __nv_bfloat16 h1 = __float2bfloat16(w1);
                        Oh[i0]      = h0;
                        Ol[i0]      = __float2bfloat16(w0 - __bfloat162float(h0));
                        Oh[i0 + 64] = h1;
                        Ol[i0 + 64] = __float2bfloat16(w1 - __bfloat162float(h1));
                    }
                } else { // MODE 3: xef scatter
                    int wch = r >> 6, kl = r & 63, b2 = col >> 10, d = col & 1023;
                    __nv_bfloat16* oh = wch ? g_xfh : g_xeh;
                    __nv_bfloat16* ol = wch ? g_xfl : g_xel;
                    store_split2(oh, ol, ((size_t)(b2 * 64 + kl)) * 1024 + d, v0, v1);
                }
            }
        }
    }
}

__global__ __launch_bounds__(256) void gemm_out(
    const __nv_bfloat16* __restrict__ Ah, const __nv_bfloat16* __restrict__ Al,
    const __nv_bfloat16* __restrict__ Bh, const __nv_bfloat16* __restrict__ Bl,
    const float* __restrict__ bias, float* __restrict__ C, int N, int K)
{
    gemm_body<0>(Ah, Al, Bh, Bl, bias, nullptr, C, nullptr, nullptr, N, K,
                 blockIdx.y * 128, blockIdx.x * 128, 0);
}
__global__ __launch_bounds__(256) void gemm_q(const float* __restrict__ bqkv)
{
    gemm_body<2>(g_xh, g_xl, g_wqh, g_wql, bqkv, nullptr, nullptr, g_qh, g_ql,
                 DIMSZ, DIMSZ, blockIdx.y * 128, blockIdx.x * 128, 0);
}
__global__ __launch_bounds__(256) void gemm_kv(const float* __restrict__ bqkv)
{
    const int which = blockIdx.z;
    gemm_body<1>(which ? g_xfh : g_xeh, which ? g_xfl : g_xel,
                 g_wqh + (size_t)(which + 1) * DIMSZ * DIMSZ,
                 g_wql + (size_t)(which + 1) * DIMSZ * DIMSZ,
                 bqkv + (which + 1) * DIMSZ, g_sef + which * KLR, nullptr,
                 which ? g_vth : g_kph, which ? g_vtl : g_kpl,
                 DIMSZ, DIMSZ, blockIdx.y * 128, blockIdx.x * 128, which);
}
__global__ __launch_bounds__(256) void gemm_xef()
{
    gemm_body<3>(g_efh, g_efl, g_xth, g_xtl, nullptr, nullptr, nullptr,
                 nullptr, nullptr, MROWS / 4, NSEQ, 0, blockIdx.x * 128, 0);
}

// ============== fp32 -> bf16 hi/lo element-wise split ========================
__global__ __launch_bounds__(256) void split_f32(
    const float* __restrict__ in, __nv_bfloat16* __restrict__ oh,
    __nv_bfloat16* __restrict__ ol, int n4)
{
    int i = blockIdx.x * 256 + threadIdx.x;
    if (i >= n4) return;
    float4 v = ((const float4*)in)[i];
    float f[4] = {v.x, v.y, v.z, v.w};
    ushort4 uh, ul;
    unsigned short* ph = &uh.x;
    unsigned short* pl = &ul.x;
    #pragma unroll
    for (int j = 0; j < 4; j++) {
        __nv_bfloat16 h = __float2bfloat16(f[j]);
        __nv_bfloat16 l = __float2bfloat16(f[j] - __bfloat162float(h));
        ph[j] = __bfloat16_as_ushort(h);
        pl[j] = __bfloat16_as_ushort(l);
    }
    ((ushort4*)oh)[i] = uh;
    ((ushort4*)ol)[i] = ul;
}

// ============== W[K][N] -> W^T[N][K] bf16 hi/lo split ========================
__global__ __launch_bounds__(256) void transpose_split(
    const float* __restrict__ W, __nv_bfloat16* __restrict__ th,
    __nv_bfloat16* __restrict__ tl, int K, int N)
{
    __shared__ float t[32][33];
    const int tx = threadIdx.x, ty = threadIdx.y;
    const int n0 = blockIdx.x * 32, k0 = blockIdx.y * 32;
    #pragma unroll
    for (int i = 0; i < 4; i++)
        t[ty + i * 8][tx] = W[(size_t)(k0 + ty + i * 8) * N + n0 + tx];
    __syncthreads();
    #pragma unroll
    for (int i = 0; i < 4; i++) {
        int n = n0 + ty + i * 8, k = k0 + tx;
        float v = t[tx][ty + i * 8];
        __nv_bfloat16 h = __float2bfloat16(v);
        th[(size_t)n * K + k] = h;
        tl[(size_t)n * K + k] = __float2bfloat16(v - __bfloat162float(h));
    }
}

// ============== column sums of E and F: g_sef[which*64+k] ====================
__global__ __launch_bounds__(256) void colsum2(const float* __restrict__ E,
                                               const float* __restrict__ F)
{
    const int which = blockIdx.x >> 6;
    const int k     = blockIdx.x & 63;
    const float* P  = which ? F : E;
    const int tid   = threadIdx.x;
    float s = 0.f;
    for (int n = tid; n < NSEQ; n += 256)
        s += P[(size_t)n * KLR + k];
    __shared__ float red[256];
    red[tid] = s;
    __syncthreads();
    #pragma unroll
    for (int off = 128; off > 0; off >>= 1) {
        if (tid < off) red[tid] += red[tid + off];
        __syncthreads();
    }
    if (tid == 0) g_sef[which * KLR + k] = red[0];
}

// =================== MMA attention: S=QKp^T, softmax, O=PV ===================
// grid (32 n-tiles, 64 bh), 256 threads (8 warps x 16 rows).
// smem: qh 16K | ql 16K | kph 8K | kpl 8K | vth 8K | vtl 8K  = 64KB
#define ATTN_SMEM 65536

__global__ __launch_bounds__(256) void attn_mma()
{
    extern __shared__ __align__(1024) char smem[];
    const uint32_t sb = smem_u32(smem);
    const int tid  = threadIdx.x;
    const int lane = tid & 31;
    const int w    = tid >> 5;
    const int bh   = blockIdx.y;
    const int b    = bh >> 4;
    const int h    = bh & 15;
    const int n0   = blockIdx.x * 128;

    // ---- async loads
    #pragma unroll
    for (int u = 0; u < 8; u++) {           // q tiles (hi then lo)
        int idx = u * 256 + tid;
        int part = idx >> 10, rem = idx & 1023, r = rem >> 3, j = rem & 7;
        const __nv_bfloat16* src =
            (part ? g_ql : g_qh) +
            ((size_t)(n0 + r) * BATCH + b) * DIMSZ + h * 64 + j * 8;
        cp16(sb + part * 16384 + sw128((uint32_t)(r * 128 + j * 16)), src);
    }
    #pragma unroll
    for (int u = 0; u < 4; u++) {           // kp tiles
        int idx = u * 256 + tid;
        int part = idx >> 9, rem = idx & 511, r = rem >> 3, j = rem & 7;
        const __nv_bfloat16* src =
            (part ? g_kpl : g_kph) + (size_t)(b * 64 + r) * DIMSZ + h * 64 + j * 8;
        cp16(sb + 32768 + part * 8192 + sw128((uint32_t)(r * 128 + j * 16)), src);
    }
    #pragma unroll
    for (int u = 0; u < 4; u++) {           // vt tiles
        int idx = u * 256 + tid;
        int part = idx >> 9, rem = idx & 511, r = rem >> 3, j = rem & 7;
        const __nv_bfloat16* src =
            (part ? g_vtl : g_vth) + (size_t)bh * 4096 + r * 64 + j * 8;
        cp16(sb + 49152 + part * 8192 + sw128((uint32_t)(r * 128 + j * 16)), src);
    }
    asm volatile("cp.async.commit_group;" ::: "memory");
    asm volatile("cp.async.wait_group 0;" ::: "memory");
    __syncthreads();

    const uint32_t sQh = sb, sQl = sb + 16384;
    const uint32_t sKh = sb + 32768, sKl = sb + 40960;
    const uint32_t sVh = sb + 49152, sVl = sb + 57344;

    // ---- S = Q @ Kp^T  (16 rows x 64 k per warp)
    float acc[8][4] = {};
    #pragma unroll
    for (int ks = 0; ks < 4; ks++) {
        uint32_t aH[4], aL[4], bH[4][4], bL[4][4];
        {
            int row = w * 16 + (lane & 15);
            int col = ks * 32 + ((lane & 16) ? 16 : 0);
            uint32_t off = sw128((uint32_t)(row * 128 + col));
            ldsm4(aH, sQh + off);
            ldsm4(aL, sQl + off);
        }
        #pragma unroll
        for (int ntp = 0; ntp < 4; ntp++) {
            int row = ntp * 16 + (lane & 7) + ((lane & 16) ? 8 : 0);
            int col = ks * 32 + ((lane & 8) ? 16 : 0);
            uint32_t off = sw128((uint32_t)(row * 128 + col));
            ldsm4(bH[ntp], sKh + off);
            ldsm4(bL[ntp], sKl + off);
        }
        #pragma unroll
        for (int ni = 0; ni < 8; ni++) {
            uint32_t b0h = bH[ni >> 1][(ni & 1) * 2];
            uint32_t b1h = bH[ni >> 1][(ni & 1) * 2 + 1];
            uint32_t b0l = bL[ni >> 1][(ni & 1) * 2];
            uint32_t b1l = bL[ni >> 1][(ni & 1) * 2 + 1];
            mma16816(acc[ni], aH, b0h, b1h);
            mma16816(acc[ni], aH, b0l, b1l);
            mma16816(acc[ni], aL, b0h, b1h);
        }
    }

    // ---- softmax over 64 k (rows: lane>>2 and lane>>2 + 8)
    const float scale = 0.125f;
    float m1 = -1e30f, m2 = -1e30f;
    #pragma unroll
    for (int ni = 0; ni < 8; ni++) {
        #pragma unroll
        for (int c = 0; c < 4; c++) acc[ni][c] *= scale;
        m1 = fmaxf(m1, fmaxf(acc[ni][0], acc[ni][1]));
        m2 = fmaxf(m2, fmaxf(acc[ni][2], acc[ni][3]));
    }
    #pragma unroll
    for (int o = 1; o <= 2; o <<= 1) {
        m1 = fmaxf(m1, __shfl_xor_sync(0xffffffffu, m1, o));
        m2 = fmaxf(m2, __shfl_xor_sync(0xffffffffu, m2, o));
    }
    float s1 = 0.f, s2 = 0.f;
    #pragma unroll
    for (int ni = 0; ni < 8; ni++) {
        acc[ni][0] = __expf(acc[ni][0] - m1);
        acc[ni][1] = __expf(acc[ni][1] - m1);
        acc[ni][2] = __expf(acc[ni][2] - m2);
        acc[ni][3] = __expf(acc[ni][3] - m2);
        s1 += acc[ni][0] + acc[ni][1];
        s2 += acc[ni][2] + acc[ni][3];
    }
    #pragma unroll
    for (int o = 1; o <= 2; o <<= 1) {
        s1 += __shfl_xor_sync(0xffffffffu, s1, o);
        s2 += __shfl_xor_sync(0xffffffffu, s2, o);
    }
    float i1 = 1.0f / s1, i2 = 1.0f / s2;
    #pragma unroll
    for (int ni = 0; ni < 8; ni++) {
        acc[ni][0] *= i1; acc[ni][1] *= i1;
        acc[ni][2] *= i2; acc[ni][3] *= i2;
    }

    // ---- P fragments -> A operands (hi/lo), O = P @ V^T
    uint32_t pH[4][4], pL[4][4];
    #pragma unroll
    for (int j = 0; j < 4; j++) {
        pH[j][0] = pack_bf16_pair(acc[2*j][0],   acc[2*j][1],   pL[j][0]);
        pH[j][1] = pack_bf16_pair(acc[2*j][2],   acc[2*j][3],   pL[j][1]);
        pH[j][2] = pack_bf16_pair(acc[2*j+1][0], acc[2*j+1][1], pL[j][2]);
        pH[j][3] = pack_bf16_pair(acc[2*j+1][2], acc[2*j+1][3], pL[j][3]);
    }
    float out[8][4] = {};
    #pragma unroll
    for (int ks = 0; ks < 4; ks++) {
        uint32_t bH[4][4], bL[4][4];
        #pragma unroll
        for (int ntp = 0; ntp < 4; ntp++) {
            int row = ntp * 16 + (lane & 7) + ((lane & 16) ? 8 : 0);
            int col = ks * 32 + ((lane & 8) ? 16 : 0);
            uint32_t off = sw128((uint32_t)(row * 128 + col));
            ldsm4(bH[ntp], sVh + off);
            ldsm4(bL[ntp], sVl + off);
        }
        #pragma unroll
        for (int ni = 0; ni < 8; ni++) {
            uint32_t b0h = bH[ni >> 1][(ni & 1) * 2];
            uint32_t b1h = bH[ni >> 1][(ni & 1) * 2 + 1];
            uint32_t b0l = bL[ni >> 1][(ni & 1) * 2];
            uint32_t b1l = bL[ni >> 1][(ni & 1) * 2 + 1];
            mma16816(out[ni], pH[ks], b0h, b1h);
            mma16816(out[ni], pH[ks], b0l, b1l);
            mma16816(out[ni], pL[ks], b0h, b1h);
        }
    }

    // ---- store attn out as bf16 hi/lo
    #pragma unroll
    for (int ni = 0; ni < 8; ni++) {
        int r1 = n0 + w * 16 + (lane >> 2);
        int d  = ni * 8 + (lane & 3) * 2;
        size_t i1x = ((size_t)r1 * BATCH + b) * DIMSZ + h * 64 + d;
        store_split2(g_aoh, g_aol, i1x, out[ni][0], out[ni][1]);
        size_t i2x = ((size_t)(r1 + 8) * BATCH + b) * DIMSZ + h * 64 + d;
        store_split2(g_aoh, g_aol, i2x, out[ni][2], out[ni][3]);
    }
}

// ---------------- launch -----------------------------------------------------
extern "C" void kernel_launch(void* const* d_in, const int* in_sizes, int n_in,
                              void* d_out, int out_size)
{
    const float* x    = (const float*)d_in[0];
    const float* E    = (const float*)d_in[1];
    const float* F    = (const float*)d_in[2];
    const float* Wqkv = (const float*)d_in[3];
    const float* bqkv = (const float*)d_in[4];
    const float* Wout = (const float*)d_in[5];
    const float* bout = (const float*)d_in[6];
    float*       out  = (float*)d_out;

    __nv_bfloat16 *xh, *xl, *xth, *xtl, *efh, *efl, *wqh, *wql, *woh, *wol,
                  *aoh, *aol;
    cudaGetSymbolAddress((void**)&xh,  g_xh);
    cudaGetSymbolAddress((void**)&xl,  g_xl);
    cudaGetSymbolAddress((void**)&xth, g_xth);
    cudaGetSymbolAddress((void**)&xtl, g_xtl);
    cudaGetSymbolAddress((void**)&efh, g_efh);
    cudaGetSymbolAddress((void**)&efl, g_efl);
    cudaGetSymbolAddress((void**)&wqh, g_wqh);
    cudaGetSymbolAddress((void**)&wql, g_wql);
    cudaGetSymbolAddress((void**)&woh, g_woh);
    cudaGetSymbolAddress((void**)&wol, g_wol);
    cudaGetSymbolAddress((void**)&aoh, g_aoh);
    cudaGetSymbolAddress((void**)&aol, g_aol);

    cudaFuncSetAttribute(gemm_out, cudaFuncAttributeMaxDynamicSharedMemorySize,
                         GEMM_SMEM);
    cudaFuncSetAttribute(gemm_q, cudaFuncAttributeMaxDynamicSharedMemorySize,
                         GEMM_SMEM);
    cudaFuncSetAttribute(gemm_kv, cudaFuncAttributeMaxDynamicSharedMemorySize,
                         GEMM_SMEM);
    cudaFuncSetAttribute(gemm_xef, cudaFuncAttributeMaxDynamicSharedMemorySize,
                         GEMM_SMEM);
    cudaFuncSetAttribute(attn_mma, cudaFuncAttributeMaxDynamicSharedMemorySize,
                         ATTN_SMEM);

    // 0) prep
    split_f32<<<(MROWS * DIMSZ / 4 + 255) / 256, 256>>>(x, xh, xl,
                                                        MROWS * DIMSZ / 4);
    transpose_split<<<dim3(QKVDIM / 32, DIMSZ / 32), dim3(32, 8)>>>(
        Wqkv, wqh, wql, DIMSZ, QKVDIM);
    transpose_split<<<dim3(DIMSZ / 32, DIMSZ / 32), dim3(32, 8)>>>(
        Wout, woh, wol, DIMSZ, DIMSZ);
    // x viewed as [n=4096][bd=4096] -> x^T splits
    transpose_split<<<dim3(MROWS / 4 / 32, NSEQ / 32), dim3(32, 8)>>>(
        x, xth, xtl, NSEQ, MROWS / 4);
    // E^T / F^T stacked (rows 0-63 / 64-127)
    transpose_split<<<dim3(KLR / 32, NSEQ / 32), dim3(32, 8)>>>(
        E, efh, efl, NSEQ, KLR);
    transpose_split<<<dim3(KLR / 32, NSEQ / 32), dim3(32, 8)>>>(
        F, efh + (size_t)KLR * NSEQ, efl + (size_t)KLR * NSEQ, NSEQ, KLR);
    colsum2<<<128, 256>>>(E, F);

    // 1) xe/xf = [E;F]^T @ x   [HMMA, 128 x 4096 x 4096]
    gemm_xef<<<dim3(32, 1), 256, GEMM_SMEM>>>();

    // 2) Q = x @ Wq + bq  -> qh/ql   [HMMA]
    gemm_q<<<dim3(DIMSZ / 128, MROWS / 128), 256, GEMM_SMEM>>>(bqkv);

    // 3) Kp/Vp (+ colsum*bias) -> kp / vt splits   [HMMA]
    gemm_kv<<<dim3(DIMSZ / 128, (BATCH * KLR) / 128, 2), 256, GEMM_SMEM>>>(bqkv);

    // 4) attention  [HMMA]
    attn_mma<<<dim3(NSEQ / 128, BATCH * NHEAD), 256, ATTN_SMEM>>>();

    // 5) out = ao @ Wout + bout   [HMMA, fp32 C]
    gemm_out<<<dim3(DIMSZ / 128, MROWS / 128), 256, GEMM_SMEM>>>(
        aoh, aol, woh, wol, bout, out, DIMSZ, DIMSZ);
}